// round 4
// baseline (speedup 1.0000x reference)
#include <cuda_runtime.h>
#include <cstdint>

// Combine: out[b, :] = branch[argmax(gate[b, 0..3])][b, :]
// B = 4096, D = 4096, N = 4, fp32. 64 MB selected-read + 64 MB write.
//
// R4: L2-residency, fixed encoding. sm_103 requires 256-bit vectors for
// L2::evict_last loads -> ld.global.nc.L2::evict_last.v8.b32 (32 B/thread).
// Read set (64 MB) pinned evict_last; write stream uses .cs (evict_first).
// Steady-state (graph replay, warm L2): DRAM carries mostly the write stream.

#define B_ROWS 4096
#define D_DIM  4096
#define THREADS 256
#define C32_PER_ROW (D_DIM * 4 / 32)              // 512 chunks of 32 B
#define C32_PER_THREAD (C32_PER_ROW / THREADS)    // 2

struct F8 { float4 lo, hi; };

__device__ __forceinline__ F8 ldg_keep8(const float* p) {
    uint32_t a0, a1, a2, a3, a4, a5, a6, a7;
    asm("ld.global.nc.L2::evict_last.v8.b32 {%0,%1,%2,%3,%4,%5,%6,%7}, [%8];"
        : "=r"(a0), "=r"(a1), "=r"(a2), "=r"(a3),
          "=r"(a4), "=r"(a5), "=r"(a6), "=r"(a7)
        : "l"(p));
    F8 v;
    v.lo.x = __uint_as_float(a0); v.lo.y = __uint_as_float(a1);
    v.lo.z = __uint_as_float(a2); v.lo.w = __uint_as_float(a3);
    v.hi.x = __uint_as_float(a4); v.hi.y = __uint_as_float(a5);
    v.hi.z = __uint_as_float(a6); v.hi.w = __uint_as_float(a7);
    return v;
}

__global__ __launch_bounds__(THREADS)
void combine_select_kernel(const float* __restrict__ b0,
                           const float* __restrict__ b1,
                           const float* __restrict__ b2,
                           const float* __restrict__ b3,
                           const float* __restrict__ gate,
                           float* __restrict__ out) {
    const int row = blockIdx.x;
    const int t = threadIdx.x;

    // Gate row = one float4 (tiny set, stays hot in L2 on its own).
    const float4 g = __ldg(reinterpret_cast<const float4*>(gate) + row);

    // argmax, first-wins ties (matches jnp.argmax).
    const float* src = b0;
    float best = g.x;
    if (g.y > best) { best = g.y; src = b1; }
    if (g.z > best) { best = g.z; src = b2; }
    if (g.w > best) { best = g.w; src = b3; }

    const float* srow = src + (size_t)row * D_DIM;
    float4* dst4 = reinterpret_cast<float4*>(out + (size_t)row * D_DIM);

    // 2 pinned 256-bit loads per thread, then 4 streaming 128-bit stores.
    F8 v[C32_PER_THREAD];
#pragma unroll
    for (int i = 0; i < C32_PER_THREAD; i++) {
        const int c = i * THREADS + t;            // 32B chunk index in row
        v[i] = ldg_keep8(srow + c * 8);
    }
#pragma unroll
    for (int i = 0; i < C32_PER_THREAD; i++) {
        const int c = i * THREADS + t;
        __stcs(dst4 + c * 2 + 0, v[i].lo);
        __stcs(dst4 + c * 2 + 1, v[i].hi);
    }
}

extern "C" void kernel_launch(void* const* d_in, const int* in_sizes, int n_in,
                              void* d_out, int out_size) {
    const float* b0   = (const float*)d_in[0];
    const float* b1   = (const float*)d_in[1];
    const float* b2   = (const float*)d_in[2];
    const float* b3   = (const float*)d_in[3];
    const float* gate = (const float*)d_in[4];
    float* out = (float*)d_out;

    combine_select_kernel<<<B_ROWS, THREADS>>>(b0, b1, b2, b3, gate, out);
}

// round 5
// speedup vs baseline: 1.0542x; 1.0542x over previous
#include <cuda_runtime.h>

// Combine: out[b, :] = branch[argmax(gate[b, 0..3])][b, :]
// B = 4096, D = 4096, N = 4, fp32. 64 MB selected-read + 64 MB write.
//
// R5: R1 geometry (best measured) + write-through stores (__stwt).
// Rationale: graph replays reuse the same 64 MB read set; it fits in the
// 126 MB L2 *if* the 64 MB write stream does not allocate. st.global.wt
// writes through to DRAM without displacing the read set, so steady-state
// replays serve all reads from L2 and DRAM carries only the write stream.

#define B_ROWS 4096
#define D_DIM  4096
#define THREADS 256
#define F4_PER_ROW (D_DIM / 4)               // 1024
#define F4_PER_THREAD (F4_PER_ROW / THREADS) // 4

__global__ __launch_bounds__(THREADS)
void combine_select_kernel(const float* __restrict__ b0,
                           const float* __restrict__ b1,
                           const float* __restrict__ b2,
                           const float* __restrict__ b3,
                           const float* __restrict__ gate,
                           float* __restrict__ out) {
    const int row = blockIdx.x;
    const int t = threadIdx.x;

    // Gate row = exactly one float4 (64 KB set, trivially L2-resident).
    const float4 g = __ldg(reinterpret_cast<const float4*>(gate) + row);

    // argmax, first-wins ties (matches jnp.argmax).
    const float* src = b0;
    float best = g.x;
    if (g.y > best) { best = g.y; src = b1; }
    if (g.z > best) { best = g.z; src = b2; }
    if (g.w > best) { best = g.w; src = b3; }

    const float4* src4 =
        reinterpret_cast<const float4*>(src + (size_t)row * D_DIM);
    float4* dst4 = reinterpret_cast<float4*>(out + (size_t)row * D_DIM);

    // 4 independent default-policy loads (allocate + persist in L2),
    // then 4 write-through stores (no L2 allocation -> no read eviction).
    float4 v[F4_PER_THREAD];
#pragma unroll
    for (int i = 0; i < F4_PER_THREAD; i++)
        v[i] = __ldg(src4 + i * THREADS + t);
#pragma unroll
    for (int i = 0; i < F4_PER_THREAD; i++)
        __stwt(dst4 + i * THREADS + t, v[i]);
}

extern "C" void kernel_launch(void* const* d_in, const int* in_sizes, int n_in,
                              void* d_out, int out_size) {
    const float* b0   = (const float*)d_in[0];
    const float* b1   = (const float*)d_in[1];
    const float* b2   = (const float*)d_in[2];
    const float* b3   = (const float*)d_in[3];
    const float* gate = (const float*)d_in[4];
    float* out = (float*)d_out;

    combine_select_kernel<<<B_ROWS, THREADS>>>(b0, b1, b2, b3, gate, out);
}